// round 3
// baseline (speedup 1.0000x reference)
#include <cuda_runtime.h>
#include <math.h>

#define H 512
#define BATCH_MAX 262144

// ---------------- device scratch (static; no runtime allocation) ----------------
__device__ float  g_u[(size_t)BATCH_MAX * 4];          // 4 MB
__device__ float  g_h1[(size_t)BATCH_MAX * H];         // 536 MB
__device__ float  g_h2[(size_t)BATCH_MAX * H];         // 536 MB (pre-BN layer2)
__device__ double g_mom[14];                           // E-sums of u and u u^T
__device__ double g_colsum[H];
__device__ double g_colsq[H];
__device__ float  g_w1eff[4 * H];
__device__ float  g_c1[H];
__device__ float  g_scale2[H];
__device__ float  g_shift2[H];

// ---------------- helpers ----------------
__device__ __forceinline__ float fast_tanh(float x) {
    float a = fabsf(x);
    float e = __expf(2.0f * a);                 // EX2-based, ~2^-21 rel err
    float r = 1.0f - __fdividef(2.0f, e + 1.0f);
    return copysignf(r, x);
}

__device__ __forceinline__ float bilerp(const float* sts, const float* stab,
                                        float xq, int j, float ty) {
    xq = fminf(fmaxf(xq, sts[0]), sts[8]);
    int ii = 0;
#pragma unroll
    for (int k = 1; k < 9; k++) if (xq >= sts[k]) ii = k;
    if (ii > 7) ii = 7;
    float tx  = (xq - sts[ii]) / (sts[ii + 1] - sts[ii]);
    float f00 = stab[ii * 14 + j];
    float f01 = stab[ii * 14 + j + 1];
    float f10 = stab[(ii + 1) * 14 + j];
    float f11 = stab[(ii + 1) * 14 + j + 1];
    return f00 * (1.0f - tx) * (1.0f - ty) + f10 * tx * (1.0f - ty)
         + f01 * (1.0f - tx) * ty          + f11 * tx * ty;
}

// ---------------- K0: zero accumulators (must run every replay) ----------------
__global__ void k_zero() {
    int t = blockIdx.x * blockDim.x + threadIdx.x;
    if (t < 14) g_mom[t] = 0.0;
    if (t < H) { g_colsum[t] = 0.0; g_colsq[t] = 0.0; }
}

// ---------------- K1: features u + 14 global moments ----------------
__global__ void k_moments(const float* __restrict__ x,
                          const float* __restrict__ ts,
                          const float* __restrict__ te,
                          const float* __restrict__ tab, int M) {
    __shared__ float sts[9], ste[14], stab[126];
    int tid = threadIdx.x;
    if (tid < 9)   sts[tid]  = ts[tid];
    if (tid < 14)  ste[tid]  = te[tid];
    if (tid < 126) stab[tid] = tab[tid];
    __syncthreads();

    int i = blockIdx.x * blockDim.x + tid;
    float u0 = 0.f, u1 = 0.f, u2 = 0.f, u3 = 0.f;
    if (i < M) {
        const float* xr = x + (size_t)i * 15;
        float amb = xr[1], sfl = xr[2], sfr = xr[3];
        float incar = xr[8], tb = xr[9], tc = xr[10];

        float yq = fminf(fmaxf(amb, ste[0]), ste[13]);
        int j = 0;
#pragma unroll
        for (int k = 1; k < 14; k++) if (yq >= ste[k]) j = k;
        if (j > 12) j = 12;
        float ty = (yq - ste[j]) / (ste[j + 1] - ste[j]);

        u0 = bilerp(sts, stab, sfl, j, ty) - incar;
        u1 = bilerp(sts, stab, sfr, j, ty) - incar;
        u2 = amb;
        u3 = tb - tc;
        *(float4*)(g_u + (size_t)i * 4) = make_float4(u0, u1, u2, u3);
    }

    double vals[14];
    vals[0] = u0; vals[1] = u1; vals[2] = u2; vals[3] = u3;
    vals[4]  = (double)u0 * u0; vals[5]  = (double)u0 * u1;
    vals[6]  = (double)u0 * u2; vals[7]  = (double)u0 * u3;
    vals[8]  = (double)u1 * u1; vals[9]  = (double)u1 * u2;
    vals[10] = (double)u1 * u3; vals[11] = (double)u2 * u2;
    vals[12] = (double)u2 * u3; vals[13] = (double)u3 * u3;
#pragma unroll
    for (int q = 0; q < 14; q++) {
        double v = vals[q];
#pragma unroll
        for (int o = 16; o > 0; o >>= 1) v += __shfl_down_sync(0xffffffffu, v, o);
        if ((tid & 31) == 0) atomicAdd(&g_mom[q], v);
    }
}

// ---------------- K1b: analytic BN1 -> effective layer-1 weights ----------------
__global__ void k_l1prep(const float* __restrict__ w1, const float* __restrict__ b1,
                         const float* __restrict__ g1, const float* __restrict__ beta1,
                         int M) {
    int j = blockIdx.x * blockDim.x + threadIdx.x;
    if (j >= H) return;
    double invB = 1.0 / (double)M;
    double m[4];
#pragma unroll
    for (int k = 0; k < 4; k++) m[k] = g_mom[k] * invB;
    double C[4][4];
    int idx = 4;
#pragma unroll
    for (int k = 0; k < 4; k++)
#pragma unroll
        for (int l = k; l < 4; l++) {
            double c = g_mom[idx++] * invB - m[k] * m[l];
            C[k][l] = c; C[l][k] = c;
        }
    float w[4];
#pragma unroll
    for (int k = 0; k < 4; k++) w[k] = w1[k * H + j];
    double mu = (double)b1[j];
#pragma unroll
    for (int k = 0; k < 4; k++) mu += m[k] * (double)w[k];
    double var = 0.0;
#pragma unroll
    for (int k = 0; k < 4; k++)
#pragma unroll
        for (int l = 0; l < 4; l++) var += (double)w[k] * (double)w[l] * C[k][l];
    float A = g1[j] * rsqrtf((float)var + 1e-5f);
#pragma unroll
    for (int k = 0; k < 4; k++) g_w1eff[k * H + j] = A * w[k];
    g_c1[j] = beta1[j] + A * (b1[j] - (float)mu);
}

// ---------------- K2a: h1 = tanh(u @ w1eff + c1) ----------------
#define K2A_ROWS 32
__global__ void k_h1(int M) {
    __shared__ float  w1s[4 * H];
    __shared__ float  c1s[H];
    __shared__ float4 us[K2A_ROWS];
    int tid = threadIdx.x;
    for (int t = tid; t < 4 * H; t += blockDim.x) w1s[t] = g_w1eff[t];
    for (int t = tid; t < H; t += blockDim.x)     c1s[t] = g_c1[t];
    int row0 = blockIdx.x * K2A_ROWS;
    for (int t = tid; t < K2A_ROWS; t += blockDim.x)
        if (row0 + t < M) us[t] = *(const float4*)(g_u + (size_t)(row0 + t) * 4);
    __syncthreads();
    for (int idx = tid; idx < K2A_ROWS * H; idx += blockDim.x) {
        int r = idx >> 9, j = idx & (H - 1);
        int row = row0 + r;
        if (row >= M) continue;
        float4 u = us[r];
        float v = c1s[j] + u.x * w1s[j] + u.y * w1s[H + j]
                         + u.z * w1s[2 * H + j] + u.w * w1s[3 * H + j];
        g_h1[(size_t)row * H + j] = fast_tanh(v);
    }
}

// ---------------- K2b: h2pre = h1 @ w2 + b2, fused column stats ----------------
// 128x128 tile, 256 threads, 8x8 micro-tile, BK=8. M assumed multiple of 128.
__global__ __launch_bounds__(256) void k_gemm(const float* __restrict__ w2,
                                              const float* __restrict__ b2, int M) {
    __shared__ float As[8][128];
    __shared__ float Bs[8][128];
    __shared__ float red[16 * 128];

    int tid = threadIdx.x;
    int tx = tid & 15, ty = tid >> 4;
    int col0 = blockIdx.x * 128;
    int row0 = blockIdx.y * 128;

    int a_r = tid >> 1, a_c = (tid & 1) * 4;
    int b_r = tid >> 5, b_c = (tid & 31) * 4;

    float acc[8][8];
#pragma unroll
    for (int i = 0; i < 8; i++)
#pragma unroll
        for (int j = 0; j < 8; j++) acc[i][j] = 0.0f;

    float bb[8];
#pragma unroll
    for (int c = 0; c < 8; c++) bb[c] = __ldg(&b2[col0 + tx * 8 + c]);

    for (int k0 = 0; k0 < H; k0 += 8) {
        float4 av = *(const float4*)(g_h1 + (size_t)(row0 + a_r) * H + k0 + a_c);
        float4 bv = *(const float4*)(w2 + (size_t)(k0 + b_r) * H + col0 + b_c);
        __syncthreads();
        As[a_c + 0][a_r] = av.x; As[a_c + 1][a_r] = av.y;
        As[a_c + 2][a_r] = av.z; As[a_c + 3][a_r] = av.w;
        *(float4*)&Bs[b_r][b_c] = bv;
        __syncthreads();
#pragma unroll
        for (int kk = 0; kk < 8; kk++) {
            float af[8], bf[8];
#pragma unroll
            for (int i = 0; i < 8; i++) af[i] = As[kk][ty * 8 + i];
#pragma unroll
            for (int j = 0; j < 8; j++) bf[j] = Bs[kk][tx * 8 + j];
#pragma unroll
            for (int i = 0; i < 8; i++)
#pragma unroll
                for (int j = 0; j < 8; j++) acc[i][j] += af[i] * bf[j];
        }
    }

    float csum[8], csq[8];
#pragma unroll
    for (int c = 0; c < 8; c++) { csum[c] = 0.f; csq[c] = 0.f; }

#pragma unroll
    for (int i = 0; i < 8; i++) {
        int row = row0 + ty * 8 + i;
        float v0[8];
#pragma unroll
        for (int j = 0; j < 8; j++) {
            float v = acc[i][j] + bb[j];
            v0[j] = v;
            csum[j] += v;
            csq[j]  += v * v;
        }
        float* cp = g_h2 + (size_t)row * H + col0 + tx * 8;
        *(float4*)(cp)     = make_float4(v0[0], v0[1], v0[2], v0[3]);
        *(float4*)(cp + 4) = make_float4(v0[4], v0[5], v0[6], v0[7]);
    }

    // column-stat reduction across ty, then one double atomic per column
#pragma unroll
    for (int c = 0; c < 8; c++) red[ty * 128 + tx * 8 + c] = csum[c];
    __syncthreads();
    if (tid < 128) {
        double s = 0.0;
#pragma unroll
        for (int t = 0; t < 16; t++) s += (double)red[t * 128 + tid];
        atomicAdd(&g_colsum[col0 + tid], s);
    }
    __syncthreads();
#pragma unroll
    for (int c = 0; c < 8; c++) red[ty * 128 + tx * 8 + c] = csq[c];
    __syncthreads();
    if (tid < 128) {
        double s = 0.0;
#pragma unroll
        for (int t = 0; t < 16; t++) s += (double)red[t * 128 + tid];
        atomicAdd(&g_colsq[col0 + tid], s);
    }
}

// ---------------- K2c: finalize BN2 scale/shift ----------------
__global__ void k_l2prep(const float* __restrict__ g2,
                         const float* __restrict__ beta2, int M) {
    int j = blockIdx.x * blockDim.x + threadIdx.x;
    if (j >= H) return;
    double mu  = g_colsum[j] / (double)M;
    double var = g_colsq[j] / (double)M - mu * mu;
    float s = g2[j] * rsqrtf((float)var + 1e-5f);
    g_scale2[j] = s;
    g_shift2[j] = beta2[j] - (float)mu * s;
}

// ---------------- K3: out = tanh(scale2*h2pre + shift2) @ w3 + b3 ----------------
__global__ void k_out(const float* __restrict__ w3, const float* __restrict__ b3,
                      float* __restrict__ out, int M) {
    __shared__ float sw[H], ss[H], sh[H];
    int tid = threadIdx.x;
    for (int t = tid; t < H; t += blockDim.x) {
        sw[t] = w3[t]; ss[t] = g_scale2[t]; sh[t] = g_shift2[t];
    }
    __syncthreads();
    int warp = tid >> 5, lane = tid & 31;
    int row = blockIdx.x * 8 + warp;
    if (row >= M) return;
    const float* hr = g_h2 + (size_t)row * H;
    float acc = 0.0f;
#pragma unroll
    for (int t = 0; t < 16; t++) {
        int j = t * 32 + lane;
        float v = fast_tanh(ss[j] * hr[j] + sh[j]);
        acc += v * sw[j];
    }
#pragma unroll
    for (int o = 16; o > 0; o >>= 1) acc += __shfl_down_sync(0xffffffffu, acc, o);
    if (lane == 0) out[row] = acc + b3[0];
}

// ---------------- launch ----------------
extern "C" void kernel_launch(void* const* d_in, const int* in_sizes, int n_in,
                              void* d_out, int out_size) {
    const float* x     = (const float*)d_in[0];
    const float* ts    = (const float*)d_in[1];
    const float* te    = (const float*)d_in[2];
    const float* tab   = (const float*)d_in[3];
    const float* w1    = (const float*)d_in[4];
    const float* b1    = (const float*)d_in[5];
    const float* g1    = (const float*)d_in[6];
    const float* beta1 = (const float*)d_in[7];
    const float* w2    = (const float*)d_in[8];
    const float* b2    = (const float*)d_in[9];
    const float* g2    = (const float*)d_in[10];
    const float* beta2 = (const float*)d_in[11];
    const float* w3    = (const float*)d_in[12];
    const float* b3    = (const float*)d_in[13];
    float* out = (float*)d_out;

    int M = in_sizes[0] / 15;

    k_zero<<<2, 256>>>();
    k_moments<<<(M + 255) / 256, 256>>>(x, ts, te, tab, M);
    k_l1prep<<<2, 256>>>(w1, b1, g1, beta1, M);
    k_h1<<<(M + K2A_ROWS - 1) / K2A_ROWS, 256>>>(M);
    k_gemm<<<dim3(4, (M + 127) / 128), 256>>>(w2, b2, M);
    k_l2prep<<<2, 256>>>(g2, beta2, M);
    k_out<<<(M + 7) / 8, 256>>>(w3, b3, out, M);
}

// round 5
// speedup vs baseline: 2.1517x; 2.1517x over previous
#include <cuda_runtime.h>
#include <cuda_bf16.h>
#include <math.h>
#include <stdint.h>

#define H 512
#define BATCH_MAX 262144

// ---------------- device scratch ----------------
__device__ float          g_u[(size_t)BATCH_MAX * 4];
__device__ __nv_bfloat16  g_h1h[(size_t)BATCH_MAX * H];   // 268 MB
__device__ __nv_bfloat16  g_h1l[(size_t)BATCH_MAX * H];   // 268 MB
__device__ float          g_h2[(size_t)BATCH_MAX * H];    // 536 MB
__device__ __nv_bfloat16  g_w2h[H * H];                   // transposed [n][k]
__device__ __nv_bfloat16  g_w2l[H * H];
__device__ double g_mom[14];
__device__ double g_colsum[H];
__device__ double g_colsq[H];
__device__ float  g_w1eff[4 * H];
__device__ float  g_c1[H];
__device__ float  g_scale2[H];
__device__ float  g_shift2[H];

// ---------------- warp-MMA helpers (baseline PTX ISA, no 'a' features) ----------------
__device__ __forceinline__ uint32_t smem_to_u32(const void* p) {
    uint32_t a;
    asm("{ .reg .u64 t; cvta.to.shared.u64 t, %1; cvt.u32.u64 %0, t; }" : "=r"(a) : "l"(p));
    return a;
}
__device__ __forceinline__ void ldsm4(uint32_t* r, uint32_t addr) {
    asm volatile("ldmatrix.sync.aligned.m8n8.x4.shared.b16 {%0,%1,%2,%3}, [%4];"
        : "=r"(r[0]), "=r"(r[1]), "=r"(r[2]), "=r"(r[3]) : "r"(addr));
}
__device__ __forceinline__ void mma_bf16(float* d, const uint32_t* a, const uint32_t* b) {
    asm volatile("mma.sync.aligned.m16n8k16.row.col.f32.bf16.bf16.f32 "
        "{%0,%1,%2,%3}, {%4,%5,%6,%7}, {%8,%9}, {%0,%1,%2,%3};"
        : "+f"(d[0]), "+f"(d[1]), "+f"(d[2]), "+f"(d[3])
        : "r"(a[0]), "r"(a[1]), "r"(a[2]), "r"(a[3]), "r"(b[0]), "r"(b[1]));
}

// ---------------- math helpers ----------------
__device__ __forceinline__ float fast_tanh(float x) {
    float a = fabsf(x);
    float e = __expf(2.0f * a);
    float r = 1.0f - __fdividef(2.0f, e + 1.0f);
    return copysignf(r, x);
}
__device__ __forceinline__ float bilerp(const float* sts, const float* stab,
                                        float xq, int j, float ty) {
    xq = fminf(fmaxf(xq, sts[0]), sts[8]);
    int ii = 0;
#pragma unroll
    for (int k = 1; k < 9; k++) if (xq >= sts[k]) ii = k;
    if (ii > 7) ii = 7;
    float tx  = (xq - sts[ii]) / (sts[ii + 1] - sts[ii]);
    float f00 = stab[ii * 14 + j], f01 = stab[ii * 14 + j + 1];
    float f10 = stab[(ii + 1) * 14 + j], f11 = stab[(ii + 1) * 14 + j + 1];
    return f00 * (1.f - tx) * (1.f - ty) + f10 * tx * (1.f - ty)
         + f01 * (1.f - tx) * ty + f11 * tx * ty;
}

// ---------------- K0: zero accumulators ----------------
__global__ void k_zero() {
    int t = blockIdx.x * blockDim.x + threadIdx.x;
    if (t < 14) g_mom[t] = 0.0;
    if (t < H) { g_colsum[t] = 0.0; g_colsq[t] = 0.0; }
}

// ---------------- K1: features + 14 moments ----------------
__global__ void k_moments(const float* __restrict__ x, const float* __restrict__ ts,
                          const float* __restrict__ te, const float* __restrict__ tab, int M) {
    __shared__ float sts[9], ste[14], stab[126];
    int tid = threadIdx.x;
    if (tid < 9)   sts[tid]  = ts[tid];
    if (tid < 14)  ste[tid]  = te[tid];
    if (tid < 126) stab[tid] = tab[tid];
    __syncthreads();
    int i = blockIdx.x * blockDim.x + tid;
    float u0 = 0.f, u1 = 0.f, u2 = 0.f, u3 = 0.f;
    if (i < M) {
        const float* xr = x + (size_t)i * 15;
        float amb = xr[1], sfl = xr[2], sfr = xr[3];
        float incar = xr[8], tb = xr[9], tc = xr[10];
        float yq = fminf(fmaxf(amb, ste[0]), ste[13]);
        int j = 0;
#pragma unroll
        for (int k = 1; k < 14; k++) if (yq >= ste[k]) j = k;
        if (j > 12) j = 12;
        float ty = (yq - ste[j]) / (ste[j + 1] - ste[j]);
        u0 = bilerp(sts, stab, sfl, j, ty) - incar;
        u1 = bilerp(sts, stab, sfr, j, ty) - incar;
        u2 = amb;
        u3 = tb - tc;
        *(float4*)(g_u + (size_t)i * 4) = make_float4(u0, u1, u2, u3);
    }
    double vals[14];
    vals[0] = u0; vals[1] = u1; vals[2] = u2; vals[3] = u3;
    vals[4]  = (double)u0 * u0; vals[5]  = (double)u0 * u1;
    vals[6]  = (double)u0 * u2; vals[7]  = (double)u0 * u3;
    vals[8]  = (double)u1 * u1; vals[9]  = (double)u1 * u2;
    vals[10] = (double)u1 * u3; vals[11] = (double)u2 * u2;
    vals[12] = (double)u2 * u3; vals[13] = (double)u3 * u3;
#pragma unroll
    for (int q = 0; q < 14; q++) {
        double v = vals[q];
#pragma unroll
        for (int o = 16; o > 0; o >>= 1) v += __shfl_down_sync(0xffffffffu, v, o);
        if ((tid & 31) == 0) atomicAdd(&g_mom[q], v);
    }
}

// ---------------- K1b: analytic BN1 ----------------
__global__ void k_l1prep(const float* __restrict__ w1, const float* __restrict__ b1,
                         const float* __restrict__ g1, const float* __restrict__ beta1, int M) {
    int j = blockIdx.x * blockDim.x + threadIdx.x;
    if (j >= H) return;
    double invB = 1.0 / (double)M;
    double m[4];
#pragma unroll
    for (int k = 0; k < 4; k++) m[k] = g_mom[k] * invB;
    double C[4][4];
    int idx = 4;
#pragma unroll
    for (int k = 0; k < 4; k++)
#pragma unroll
        for (int l = k; l < 4; l++) {
            double c = g_mom[idx++] * invB - m[k] * m[l];
            C[k][l] = c; C[l][k] = c;
        }
    float w[4];
#pragma unroll
    for (int k = 0; k < 4; k++) w[k] = w1[k * H + j];
    double mu = (double)b1[j];
#pragma unroll
    for (int k = 0; k < 4; k++) mu += m[k] * (double)w[k];
    double var = 0.0;
#pragma unroll
    for (int k = 0; k < 4; k++)
#pragma unroll
        for (int l = 0; l < 4; l++) var += (double)w[k] * (double)w[l] * C[k][l];
    float A = g1[j] * rsqrtf((float)var + 1e-5f);
#pragma unroll
    for (int k = 0; k < 4; k++) g_w1eff[k * H + j] = A * w[k];
    g_c1[j] = beta1[j] + A * (b1[j] - (float)mu);
}

// ---------------- K1c: split + transpose w2 -> [n][k] bf16 hi/lo ----------------
__global__ void k_w2split(const float* __restrict__ w2) {
    int idx = blockIdx.x * 256 + threadIdx.x;   // 0..262143
    int k = idx >> 9, n = idx & (H - 1);
    float v = __ldg(&w2[(size_t)k * H + n]);
    __nv_bfloat16 hi = __float2bfloat16_rn(v);
    float lo = v - __bfloat162float(hi);
    g_w2h[(size_t)n * H + k] = hi;
    g_w2l[(size_t)n * H + k] = __float2bfloat16_rn(lo);
}

// ---------------- K2a: h1 = tanh(u @ w1eff + c1), bf16 hi/lo split ----------------
__global__ __launch_bounds__(256) void k_h1(int M) {
    __shared__ float w1s[4 * H], c1s[H];
    int tid = threadIdx.x;
    for (int t = tid; t < 4 * H; t += 256) w1s[t] = g_w1eff[t];
    for (int t = tid; t < H;     t += 256) c1s[t] = g_c1[t];
    __syncthreads();
    int row0 = blockIdx.x * 32;
    int j0 = (tid & 63) * 8;
#pragma unroll
    for (int pass = 0; pass < 8; pass++) {
        int r = row0 + pass * 4 + (tid >> 6);
        if (r >= M) continue;
        float4 u = *(const float4*)(g_u + (size_t)r * 4);
        __nv_bfloat16 hi[8], lo[8];
#pragma unroll
        for (int i = 0; i < 8; i++) {
            int j = j0 + i;
            float v = c1s[j] + u.x * w1s[j] + u.y * w1s[H + j]
                             + u.z * w1s[2 * H + j] + u.w * w1s[3 * H + j];
            v = fast_tanh(v);
            hi[i] = __float2bfloat16_rn(v);
            lo[i] = __float2bfloat16_rn(v - __bfloat162float(hi[i]));
        }
        *(uint4*)(g_h1h + (size_t)r * H + j0) = *(uint4*)hi;
        *(uint4*)(g_h1l + (size_t)r * H + j0) = *(uint4*)lo;
    }
}

// ---------------- K2b: warp-MMA split-bf16 GEMM h2pre = h1 @ w2 + b2 ----------------
// CTA 128x128, 8 warps (4m x 2n), warp tile 32x64, K-chunk 32, 16 chunks.
// SMEM rows padded to 80 B (32 bf16 = 64 B data + 16 B pad) -> conflict-free ldmatrix.
#define PAD 80
#define SA_H 0
#define SA_L 10240
#define SB_H 20480
#define SB_L 30720

__global__ void __launch_bounds__(256, 2) k_gemm_mma(const float* __restrict__ b2, int M) {
    __shared__ __align__(16) char smem[4 * 10240];
    uint32_t sb = smem_to_u32(smem);
    int tid = threadIdx.x, lane = tid & 31, wid = tid >> 5;
    int wm = wid & 3, wn = wid >> 2;
    int rowBase = blockIdx.x * 128;
    int colBase = blockIdx.y * 128;

    // per-lane ldmatrix offsets (8x8 b16 tiles, canonical x4 ordering)
    uint32_t a_off = ((lane & 7) + ((lane >> 3) & 1) * 8) * PAD + ((lane >> 4) & 1) * 16;
    uint32_t b_off = ((lane & 7) + ((lane >> 4) & 1) * 8) * PAD + ((lane >> 3) & 1) * 16;
    uint32_t aH = sb + SA_H + (wm * 32) * PAD + a_off;
    uint32_t aL = sb + SA_L + (wm * 32) * PAD + a_off;
    uint32_t bH = sb + SB_H + (wn * 64) * PAD + b_off;
    uint32_t bL = sb + SB_L + (wn * 64) * PAD + b_off;

    float acc[2][8][4];
#pragma unroll
    for (int i = 0; i < 2; i++)
#pragma unroll
        for (int j = 0; j < 8; j++)
#pragma unroll
            for (int q = 0; q < 4; q++) acc[i][j][q] = 0.0f;

    for (int c = 0; c < 16; c++) {
        int k0 = c * 32;
        // load A hi/lo: 2 x 128 rows x 4 x uint4
        for (int i = tid; i < 1024; i += 256) {
            int arr = i >> 9, rem = i & 511;
            int row = rem >> 2, seg = rem & 3;
            int rr = rowBase + row; if (rr >= M) rr = M - 1;
            const __nv_bfloat16* src = arr ? g_h1l : g_h1h;
            uint4 v = *(const uint4*)(src + (size_t)rr * H + k0 + seg * 8);
            *(uint4*)(smem + (arr ? SA_L : SA_H) + row * PAD + seg * 16) = v;
        }
        // load B hi/lo: 2 x 128 n-rows x 4 x uint4
        for (int i = tid; i < 1024; i += 256) {
            int arr = i >> 9, rem = i & 511;
            int n = rem >> 2, seg = rem & 3;
            const __nv_bfloat16* src = arr ? g_w2l : g_w2h;
            uint4 v = *(const uint4*)(src + (size_t)(colBase + n) * H + k0 + seg * 8);
            *(uint4*)(smem + (arr ? SB_L : SB_H) + n * PAD + seg * 16) = v;
        }
        __syncthreads();

#pragma unroll
        for (int kk = 0; kk < 2; kk++) {
            uint32_t kb = kk * 32;   // 16 bf16 = 32 bytes
            uint32_t ah0[4], ah1[4], al0[4], al1[4];
            ldsm4(ah0, aH + kb);
            ldsm4(ah1, aH + 16 * PAD + kb);
            ldsm4(al0, aL + kb);
            ldsm4(al1, aL + 16 * PAD + kb);
#pragma unroll
            for (int nq = 0; nq < 4; nq++) {
                uint32_t bh[4], bl[4];
                ldsm4(bh, bH + nq * 16 * PAD + kb);
                ldsm4(bl, bL + nq * 16 * PAD + kb);
#pragma unroll
                for (int hh = 0; hh < 2; hh++) {
                    int nt = nq * 2 + hh;
                    mma_bf16(acc[0][nt], ah0, &bh[hh * 2]);
                    mma_bf16(acc[1][nt], ah1, &bh[hh * 2]);
                    mma_bf16(acc[0][nt], ah0, &bl[hh * 2]);
                    mma_bf16(acc[1][nt], ah1, &bl[hh * 2]);
                    mma_bf16(acc[0][nt], al0, &bh[hh * 2]);
                    mma_bf16(acc[1][nt], al1, &bh[hh * 2]);
                }
            }
        }
        __syncthreads();
    }

    // epilogue: add bias, store h2pre
    int gid = lane >> 2, t4 = lane & 3;
#pragma unroll
    for (int nt = 0; nt < 8; nt++) {
        int col = colBase + wn * 64 + nt * 8 + t4 * 2;
        float2 bb = *(const float2*)(b2 + col);
#pragma unroll
        for (int mt = 0; mt < 2; mt++) {
            int r1 = rowBase + wm * 32 + mt * 16 + gid;
            int r2 = r1 + 8;
            if (r1 < M) {
                float2 v0 = make_float2(acc[mt][nt][0] + bb.x, acc[mt][nt][1] + bb.y);
                *(float2*)(g_h2 + (size_t)r1 * H + col) = v0;
            }
            if (r2 < M) {
                float2 v1 = make_float2(acc[mt][nt][2] + bb.x, acc[mt][nt][3] + bb.y);
                *(float2*)(g_h2 + (size_t)r2 * H + col) = v1;
            }
        }
    }
}

// ---------------- K2c: column stats over h2pre ----------------
__global__ __launch_bounds__(256) void k_stats(int M) {
    int jg = threadIdx.x & 127;
    int j = jg * 4;
    int r = blockIdx.x * 2 + (threadIdx.x >> 7);
    float s0 = 0, s1 = 0, s2 = 0, s3 = 0, q0 = 0, q1 = 0, q2 = 0, q3 = 0;
    int stride = gridDim.x * 2;
    for (; r < M; r += stride) {
        float4 v = *(const float4*)(g_h2 + (size_t)r * H + j);
        s0 += v.x; q0 += v.x * v.x;
        s1 += v.y; q1 += v.y * v.y;
        s2 += v.z; q2 += v.z * v.z;
        s3 += v.w; q3 += v.w * v.w;
    }
    atomicAdd(&g_colsum[j + 0], (double)s0);
    atomicAdd(&g_colsum[j + 1], (double)s1);
    atomicAdd(&g_colsum[j + 2], (double)s2);
    atomicAdd(&g_colsum[j + 3], (double)s3);
    atomicAdd(&g_colsq[j + 0], (double)q0);
    atomicAdd(&g_colsq[j + 1], (double)q1);
    atomicAdd(&g_colsq[j + 2], (double)q2);
    atomicAdd(&g_colsq[j + 3], (double)q3);
}

// ---------------- K2d: BN2 scale/shift ----------------
__global__ void k_l2prep(const float* __restrict__ g2, const float* __restrict__ beta2, int M) {
    int j = blockIdx.x * blockDim.x + threadIdx.x;
    if (j >= H) return;
    double mu  = g_colsum[j] / (double)M;
    double var = g_colsq[j] / (double)M - mu * mu;
    float s = g2[j] * rsqrtf((float)var + 1e-5f);
    g_scale2[j] = s;
    g_shift2[j] = beta2[j] - (float)mu * s;
}

// ---------------- K3: out = tanh(s*h2pre + t) @ w3 + b3 ----------------
__global__ void k_out(const float* __restrict__ w3, const float* __restrict__ b3,
                      float* __restrict__ out, int M) {
    __shared__ float sw[H], ss[H], sh[H];
    int tid = threadIdx.x;
    for (int t = tid; t < H; t += blockDim.x) {
        sw[t] = w3[t]; ss[t] = g_scale2[t]; sh[t] = g_shift2[t];
    }
    __syncthreads();
    int warp = tid >> 5, lane = tid & 31;
    int row = blockIdx.x * 8 + warp;
    if (row >= M) return;
    const float* hr = g_h2 + (size_t)row * H;
    float acc = 0.0f;
#pragma unroll
    for (int t = 0; t < 16; t++) {
        int j = t * 32 + lane;
        float v = fast_tanh(ss[j] * hr[j] + sh[j]);
        acc += v * sw[j];
    }
#pragma unroll
    for (int o = 16; o > 0; o >>= 1) acc += __shfl_down_sync(0xffffffffu, acc, o);
    if (lane == 0) out[row] = acc + b3[0];
}

// ---------------- launch ----------------
extern "C" void kernel_launch(void* const* d_in, const int* in_sizes, int n_in,
                              void* d_out, int out_size) {
    const float* x     = (const float*)d_in[0];
    const float* ts    = (const float*)d_in[1];
    const float* te    = (const float*)d_in[2];
    const float* tab   = (const float*)d_in[3];
    const float* w1    = (const float*)d_in[4];
    const float* b1    = (const float*)d_in[5];
    const float* g1    = (const float*)d_in[6];
    const float* beta1 = (const float*)d_in[7];
    const float* w2    = (const float*)d_in[8];
    const float* b2    = (const float*)d_in[9];
    const float* g2    = (const float*)d_in[10];
    const float* beta2 = (const float*)d_in[11];
    const float* w3    = (const float*)d_in[12];
    const float* b3    = (const float*)d_in[13];
    float* out = (float*)d_out;

    int M = in_sizes[0] / 15;

    k_zero<<<2, 256>>>();
    k_moments<<<(M + 255) / 256, 256>>>(x, ts, te, tab, M);
    k_l1prep<<<2, 256>>>(w1, b1, g1, beta1, M);
    k_w2split<<<(H * H) / 256, 256>>>(w2);
    k_h1<<<(M + 31) / 32, 256>>>(M);
    k_gemm_mma<<<dim3((M + 127) / 128, 4), 256>>>(b2, M);
    k_stats<<<256, 256>>>(M);
    k_l2prep<<<2, 256>>>(g2, beta2, M);
    k_out<<<(M + 7) / 8, 256>>>(w3, b3, out, M);
}

// round 6
// speedup vs baseline: 3.5822x; 1.6649x over previous
#include <cuda_runtime.h>
#include <cuda_bf16.h>
#include <math.h>
#include <stdint.h>

#define H 512
#define BATCH_MAX 262144

// ---------------- device scratch ----------------
__device__ float          g_u[(size_t)BATCH_MAX * 4];
__device__ __nv_bfloat16  g_h1h[(size_t)BATCH_MAX * H];   // 268 MB
__device__ __nv_bfloat16  g_h1l[(size_t)BATCH_MAX * H];   // 268 MB
__device__ float          g_h2[(size_t)BATCH_MAX * H];    // 536 MB
__device__ __nv_bfloat16  g_w2h[H * H];                   // transposed [n][k]
__device__ __nv_bfloat16  g_w2l[H * H];
__device__ double g_mom[14];
__device__ double g_colsum[H];
__device__ double g_colsq[H];
__device__ float  g_w1eff[4 * H];
__device__ float  g_c1[H];
__device__ float  g_scale2[H];
__device__ float  g_shift2[H];

// ---------------- PTX helpers (baseline ISA only) ----------------
__device__ __forceinline__ uint32_t smem_to_u32(const void* p) {
    uint32_t a;
    asm("{ .reg .u64 t; cvta.to.shared.u64 t, %1; cvt.u32.u64 %0, t; }" : "=r"(a) : "l"(p));
    return a;
}
__device__ __forceinline__ void ldsm4(uint32_t* r, uint32_t addr) {
    asm volatile("ldmatrix.sync.aligned.m8n8.x4.shared.b16 {%0,%1,%2,%3}, [%4];"
        : "=r"(r[0]), "=r"(r[1]), "=r"(r[2]), "=r"(r[3]) : "r"(addr));
}
__device__ __forceinline__ void mma_bf16(float* d, const uint32_t* a, const uint32_t* b) {
    asm volatile("mma.sync.aligned.m16n8k16.row.col.f32.bf16.bf16.f32 "
        "{%0,%1,%2,%3}, {%4,%5,%6,%7}, {%8,%9}, {%0,%1,%2,%3};"
        : "+f"(d[0]), "+f"(d[1]), "+f"(d[2]), "+f"(d[3])
        : "r"(a[0]), "r"(a[1]), "r"(a[2]), "r"(a[3]), "r"(b[0]), "r"(b[1]));
}
__device__ __forceinline__ void cp16(uint32_t dst, const void* src) {
    asm volatile("cp.async.cg.shared.global [%0], [%1], 16;" :: "r"(dst), "l"(src));
}
#define CP_COMMIT() asm volatile("cp.async.commit_group;" ::: "memory")
#define CP_WAIT(n)  asm volatile("cp.async.wait_group %0;" :: "n"(n) : "memory")

// ---------------- math helpers ----------------
__device__ __forceinline__ float fast_tanh(float x) {
    float a = fabsf(x);
    float e = __expf(2.0f * a);
    float r = 1.0f - __fdividef(2.0f, e + 1.0f);
    return copysignf(r, x);
}
__device__ __forceinline__ float bilerp(const float* sts, const float* stab,
                                        float xq, int j, float ty) {
    xq = fminf(fmaxf(xq, sts[0]), sts[8]);
    int ii = 0;
#pragma unroll
    for (int k = 1; k < 9; k++) if (xq >= sts[k]) ii = k;
    if (ii > 7) ii = 7;
    float tx  = (xq - sts[ii]) / (sts[ii + 1] - sts[ii]);
    float f00 = stab[ii * 14 + j], f01 = stab[ii * 14 + j + 1];
    float f10 = stab[(ii + 1) * 14 + j], f11 = stab[(ii + 1) * 14 + j + 1];
    return f00 * (1.f - tx) * (1.f - ty) + f10 * tx * (1.f - ty)
         + f01 * (1.f - tx) * ty + f11 * tx * ty;
}

// ---------------- K0 ----------------
__global__ void k_zero() {
    int t = blockIdx.x * blockDim.x + threadIdx.x;
    if (t < 14) g_mom[t] = 0.0;
    if (t < H) { g_colsum[t] = 0.0; g_colsq[t] = 0.0; }
}

// ---------------- K1: features + 14 moments ----------------
__global__ void k_moments(const float* __restrict__ x, const float* __restrict__ ts,
                          const float* __restrict__ te, const float* __restrict__ tab, int M) {
    __shared__ float sts[9], ste[14], stab[126];
    int tid = threadIdx.x;
    if (tid < 9)   sts[tid]  = ts[tid];
    if (tid < 14)  ste[tid]  = te[tid];
    if (tid < 126) stab[tid] = tab[tid];
    __syncthreads();
    int i = blockIdx.x * blockDim.x + tid;
    float u0 = 0.f, u1 = 0.f, u2 = 0.f, u3 = 0.f;
    if (i < M) {
        const float* xr = x + (size_t)i * 15;
        float amb = xr[1], sfl = xr[2], sfr = xr[3];
        float incar = xr[8], tb = xr[9], tc = xr[10];
        float yq = fminf(fmaxf(amb, ste[0]), ste[13]);
        int j = 0;
#pragma unroll
        for (int k = 1; k < 14; k++) if (yq >= ste[k]) j = k;
        if (j > 12) j = 12;
        float ty = (yq - ste[j]) / (ste[j + 1] - ste[j]);
        u0 = bilerp(sts, stab, sfl, j, ty) - incar;
        u1 = bilerp(sts, stab, sfr, j, ty) - incar;
        u2 = amb;
        u3 = tb - tc;
        *(float4*)(g_u + (size_t)i * 4) = make_float4(u0, u1, u2, u3);
    }
    double vals[14];
    vals[0] = u0; vals[1] = u1; vals[2] = u2; vals[3] = u3;
    vals[4]  = (double)u0 * u0; vals[5]  = (double)u0 * u1;
    vals[6]  = (double)u0 * u2; vals[7]  = (double)u0 * u3;
    vals[8]  = (double)u1 * u1; vals[9]  = (double)u1 * u2;
    vals[10] = (double)u1 * u3; vals[11] = (double)u2 * u2;
    vals[12] = (double)u2 * u3; vals[13] = (double)u3 * u3;
#pragma unroll
    for (int q = 0; q < 14; q++) {
        double v = vals[q];
#pragma unroll
        for (int o = 16; o > 0; o >>= 1) v += __shfl_down_sync(0xffffffffu, v, o);
        if ((tid & 31) == 0) atomicAdd(&g_mom[q], v);
    }
}

// ---------------- K1b: analytic BN1 ----------------
__global__ void k_l1prep(const float* __restrict__ w1, const float* __restrict__ b1,
                         const float* __restrict__ g1, const float* __restrict__ beta1, int M) {
    int j = blockIdx.x * blockDim.x + threadIdx.x;
    if (j >= H) return;
    double invB = 1.0 / (double)M;
    double m[4];
#pragma unroll
    for (int k = 0; k < 4; k++) m[k] = g_mom[k] * invB;
    double C[4][4];
    int idx = 4;
#pragma unroll
    for (int k = 0; k < 4; k++)
#pragma unroll
        for (int l = k; l < 4; l++) {
            double c = g_mom[idx++] * invB - m[k] * m[l];
            C[k][l] = c; C[l][k] = c;
        }
    float w[4];
#pragma unroll
    for (int k = 0; k < 4; k++) w[k] = w1[k * H + j];
    double mu = (double)b1[j];
#pragma unroll
    for (int k = 0; k < 4; k++) mu += m[k] * (double)w[k];
    double var = 0.0;
#pragma unroll
    for (int k = 0; k < 4; k++)
#pragma unroll
        for (int l = 0; l < 4; l++) var += (double)w[k] * (double)w[l] * C[k][l];
    float A = g1[j] * rsqrtf((float)var + 1e-5f);
#pragma unroll
    for (int k = 0; k < 4; k++) g_w1eff[k * H + j] = A * w[k];
    g_c1[j] = beta1[j] + A * (b1[j] - (float)mu);
}

// ---------------- K1c: split + transpose w2 ----------------
__global__ void k_w2split(const float* __restrict__ w2) {
    int idx = blockIdx.x * 256 + threadIdx.x;
    int k = idx >> 9, n = idx & (H - 1);
    float v = __ldg(&w2[(size_t)k * H + n]);
    __nv_bfloat16 hi = __float2bfloat16_rn(v);
    float lo = v - __bfloat162float(hi);
    g_w2h[(size_t)n * H + k] = hi;
    g_w2l[(size_t)n * H + k] = __float2bfloat16_rn(lo);
}

// ---------------- K2a: h1 = tanh(u @ w1eff + c1), bf16 hi/lo split ----------------
__global__ __launch_bounds__(256) void k_h1(int M) {
    __shared__ float w1s[4 * H], c1s[H];
    int tid = threadIdx.x;
    for (int t = tid; t < 4 * H; t += 256) w1s[t] = g_w1eff[t];
    for (int t = tid; t < H;     t += 256) c1s[t] = g_c1[t];
    __syncthreads();
    int row0 = blockIdx.x * 32;
    int j0 = (tid & 63) * 8;
#pragma unroll
    for (int pass = 0; pass < 8; pass++) {
        int r = row0 + pass * 4 + (tid >> 6);
        if (r >= M) continue;
        float4 u = *(const float4*)(g_u + (size_t)r * 4);
        __nv_bfloat16 hi[8], lo[8];
#pragma unroll
        for (int i = 0; i < 8; i++) {
            int j = j0 + i;
            float v = c1s[j] + u.x * w1s[j] + u.y * w1s[H + j]
                             + u.z * w1s[2 * H + j] + u.w * w1s[3 * H + j];
            v = fast_tanh(v);
            hi[i] = __float2bfloat16_rn(v);
            lo[i] = __float2bfloat16_rn(v - __bfloat162float(hi[i]));
        }
        *(uint4*)(g_h1h + (size_t)r * H + j0) = *(uint4*)hi;
        *(uint4*)(g_h1l + (size_t)r * H + j0) = *(uint4*)lo;
    }
}

// ---------------- K2b: pipelined warp-MMA split-bf16 GEMM + fused column stats ----
// CTA 128x128, 8 warps (4m x 2n), K-chunk 32, 16 chunks, 2-stage cp.async pipeline.
// grid = (4 col blocks, M/128 row blocks): col CTAs of one row block are adjacent
// in launch order -> A row block read once from DRAM, 3x from L2.
#define PADB 80
#define STG_A_H 0
#define STG_A_L 10240
#define STG_B_H 20480
#define STG_B_L 30720
#define STG_SZ  40960
#define SMEM_GEMM (2 * STG_SZ)

__global__ void __launch_bounds__(256, 2) k_gemm_mma(const float* __restrict__ b2, int M) {
    extern __shared__ __align__(16) char smem[];
    uint32_t sb = smem_to_u32(smem);
    int tid = threadIdx.x, lane = tid & 31, wid = tid >> 5;
    int wm = wid & 3, wn = wid >> 2;
    int colBase = blockIdx.x * 128;
    int rowBase = blockIdx.y * 128;

    // per-lane ldmatrix offsets
    uint32_t a_off = ((lane & 7) + ((lane >> 3) & 1) * 8) * PADB + ((lane >> 4) & 1) * 16;
    uint32_t b_off = ((lane & 7) + ((lane >> 4) & 1) * 8) * PADB + ((lane >> 3) & 1) * 16;

    // cp.async load indices (4 A-iters + 4 B-iters per thread)
    int la_arr = tid >> 7;            // 0..1 over 2 iters? recompute in loop instead
    (void)la_arr;

    float acc[2][8][4];
#pragma unroll
    for (int i = 0; i < 2; i++)
#pragma unroll
        for (int j = 0; j < 8; j++)
#pragma unroll
            for (int q = 0; q < 4; q++) acc[i][j][q] = 0.0f;

#define LOAD_CHUNK(c, s) do {                                                       \
        int k0_ = (c) * 32;                                                         \
        uint32_t base_ = sb + (s) * STG_SZ;                                         \
        _Pragma("unroll")                                                           \
        for (int i_ = tid; i_ < 1024; i_ += 256) {                                  \
            int arr_ = i_ >> 9, rem_ = i_ & 511;                                    \
            int row_ = rem_ >> 2, seg_ = rem_ & 3;                                  \
            int rr_ = rowBase + row_; if (rr_ >= M) rr_ = M - 1;                    \
            const __nv_bfloat16* src_ = (arr_ ? g_h1l : g_h1h)                      \
                + (size_t)rr_ * H + k0_ + seg_ * 8;                                 \
            cp16(base_ + (arr_ ? STG_A_L : STG_A_H) + row_ * PADB + seg_ * 16, src_); \
        }                                                                           \
        _Pragma("unroll")                                                           \
        for (int i_ = tid; i_ < 1024; i_ += 256) {                                  \
            int arr_ = i_ >> 9, rem_ = i_ & 511;                                    \
            int n_ = rem_ >> 2, seg_ = rem_ & 3;                                    \
            const __nv_bfloat16* src_ = (arr_ ? g_w2l : g_w2h)                      \
                + (size_t)(colBase + n_) * H + k0_ + seg_ * 8;                      \
            cp16(base_ + (arr_ ? STG_B_L : STG_B_H) + n_ * PADB + seg_ * 16, src_); \
        }                                                                           \
    } while (0)

    LOAD_CHUNK(0, 0);
    CP_COMMIT();

    for (int c = 0; c < 16; c++) {
        int s = c & 1;
        if (c < 15) {
            LOAD_CHUNK(c + 1, s ^ 1);
            CP_COMMIT();
            CP_WAIT(1);
        } else {
            CP_WAIT(0);
        }
        __syncthreads();

        uint32_t stg = sb + s * STG_SZ;
        uint32_t aH = stg + STG_A_H + (wm * 32) * PADB + a_off;
        uint32_t aL = stg + STG_A_L + (wm * 32) * PADB + a_off;
        uint32_t bHp = stg + STG_B_H + (wn * 64) * PADB + b_off;
        uint32_t bLp = stg + STG_B_L + (wn * 64) * PADB + b_off;

#pragma unroll
        for (int kk = 0; kk < 2; kk++) {
            uint32_t kb = kk * 32;
            uint32_t ah0[4], ah1[4], al0[4], al1[4];
            ldsm4(ah0, aH + kb);
            ldsm4(ah1, aH + 16 * PADB + kb);
            ldsm4(al0, aL + kb);
            ldsm4(al1, aL + 16 * PADB + kb);
#pragma unroll
            for (int nq = 0; nq < 4; nq++) {
                uint32_t bh[4], bl[4];
                ldsm4(bh, bHp + nq * 16 * PADB + kb);
                ldsm4(bl, bLp + nq * 16 * PADB + kb);
#pragma unroll
                for (int hh = 0; hh < 2; hh++) {
                    int nt = nq * 2 + hh;
                    mma_bf16(acc[0][nt], ah0, &bh[hh * 2]);
                    mma_bf16(acc[1][nt], ah1, &bh[hh * 2]);
                    mma_bf16(acc[0][nt], ah0, &bl[hh * 2]);
                    mma_bf16(acc[1][nt], ah1, &bl[hh * 2]);
                    mma_bf16(acc[0][nt], al0, &bh[hh * 2]);
                    mma_bf16(acc[1][nt], al1, &bh[hh * 2]);
                }
            }
        }
        __syncthreads();
    }

    // ---- epilogue: bias add, h2 store, fused column stats ----
    float* s_sum = (float*)smem;          // reuse pipeline smem (free now)
    float* s_sq  = (float*)smem + 128;
    if (tid < 128) { s_sum[tid] = 0.f; s_sq[tid] = 0.f; }
    __syncthreads();

    int gid = lane >> 2, t4 = lane & 3;
#pragma unroll
    for (int nt = 0; nt < 8; nt++) {
        int colLocal = wn * 64 + nt * 8 + t4 * 2;
        int col = colBase + colLocal;
        float2 bb = *(const float2*)(b2 + col);
        float s0 = 0.f, s1 = 0.f, q0 = 0.f, q1 = 0.f;
#pragma unroll
        for (int mt = 0; mt < 2; mt++) {
            int r1 = rowBase + wm * 32 + mt * 16 + gid;
            int r2 = r1 + 8;
            float v00 = acc[mt][nt][0] + bb.x, v01 = acc[mt][nt][1] + bb.y;
            float v10 = acc[mt][nt][2] + bb.x, v11 = acc[mt][nt][3] + bb.y;
            if (r1 < M) *(float2*)(g_h2 + (size_t)r1 * H + col) = make_float2(v00, v01);
            if (r2 < M) *(float2*)(g_h2 + (size_t)r2 * H + col) = make_float2(v10, v11);
            s0 += v00 + v10; s1 += v01 + v11;
            q0 += v00 * v00 + v10 * v10;
            q1 += v01 * v01 + v11 * v11;
        }
        // reduce over gid (lanes strided by 4): offsets 16, 8, 4
#pragma unroll
        for (int o = 16; o >= 4; o >>= 1) {
            s0 += __shfl_down_sync(0xffffffffu, s0, o);
            s1 += __shfl_down_sync(0xffffffffu, s1, o);
            q0 += __shfl_down_sync(0xffffffffu, q0, o);
            q1 += __shfl_down_sync(0xffffffffu, q1, o);
        }
        if (lane < 4) {
            int cl = wn * 64 + nt * 8 + lane * 2;
            atomicAdd(&s_sum[cl],     s0);
            atomicAdd(&s_sum[cl + 1], s1);
            atomicAdd(&s_sq[cl],      q0);
            atomicAdd(&s_sq[cl + 1],  q1);
        }
    }
    __syncthreads();
    if (tid < 128) {
        atomicAdd(&g_colsum[colBase + tid], (double)s_sum[tid]);
        atomicAdd(&g_colsq[colBase + tid],  (double)s_sq[tid]);
    }
}

// ---------------- K2d: BN2 scale/shift ----------------
__global__ void k_l2prep(const float* __restrict__ g2, const float* __restrict__ beta2, int M) {
    int j = blockIdx.x * blockDim.x + threadIdx.x;
    if (j >= H) return;
    double mu  = g_colsum[j] / (double)M;
    double var = g_colsq[j] / (double)M - mu * mu;
    float s = g2[j] * rsqrtf((float)var + 1e-5f);
    g_scale2[j] = s;
    g_shift2[j] = beta2[j] - (float)mu * s;
}

// ---------------- K3: out = tanh(s*h2pre + t) @ w3 + b3 ----------------
__global__ void k_out(const float* __restrict__ w3, const float* __restrict__ b3,
                      float* __restrict__ out, int M) {
    __shared__ float sw[H], ss[H], sh[H];
    int tid = threadIdx.x;
    for (int t = tid; t < H; t += blockDim.x) {
        sw[t] = w3[t]; ss[t] = g_scale2[t]; sh[t] = g_shift2[t];
    }
    __syncthreads();
    int warp = tid >> 5, lane = tid & 31;
    int row = blockIdx.x * 8 + warp;
    if (row >= M) return;
    const float* hr = g_h2 + (size_t)row * H;
    float acc = 0.0f;
#pragma unroll
    for (int t = 0; t < 16; t++) {
        int j = t * 32 + lane;
        float v = fast_tanh(ss[j] * hr[j] + sh[j]);
        acc += v * sw[j];
    }
#pragma unroll
    for (int o = 16; o > 0; o >>= 1) acc += __shfl_down_sync(0xffffffffu, acc, o);
    if (lane == 0) out[row] = acc + b3[0];
}

// ---------------- launch ----------------
extern "C" void kernel_launch(void* const* d_in, const int* in_sizes, int n_in,
                              void* d_out, int out_size) {
    const float* x     = (const float*)d_in[0];
    const float* ts    = (const float*)d_in[1];
    const float* te    = (const float*)d_in[2];
    const float* tab   = (const float*)d_in[3];
    const float* w1    = (const float*)d_in[4];
    const float* b1    = (const float*)d_in[5];
    const float* g1    = (const float*)d_in[6];
    const float* beta1 = (const float*)d_in[7];
    const float* w2    = (const float*)d_in[8];
    const float* b2    = (const float*)d_in[9];
    const float* g2    = (const float*)d_in[10];
    const float* beta2 = (const float*)d_in[11];
    const float* w3    = (const float*)d_in[12];
    const float* b3    = (const float*)d_in[13];
    float* out = (float*)d_out;

    int M = in_sizes[0] / 15;

    cudaFuncSetAttribute(k_gemm_mma, cudaFuncAttributeMaxDynamicSharedMemorySize, SMEM_GEMM);

    k_zero<<<2, 256>>>();
    k_moments<<<(M + 255) / 256, 256>>>(x, ts, te, tab, M);
    k_l1prep<<<2, 256>>>(w1, b1, g1, beta1, M);
    k_w2split<<<(H * H) / 256, 256>>>(w2);
    k_h1<<<(M + 31) / 32, 256>>>(M);
    k_gemm_mma<<<dim3(4, (M + 127) / 128), 256, SMEM_GEMM>>>(b2, M);
    k_l2prep<<<2, 256>>>(g2, beta2, M);
    k_out<<<(M + 7) / 8, 256>>>(w3, b3, out, M);
}

// round 7
// speedup vs baseline: 5.9435x; 1.6592x over previous
#include <cuda_runtime.h>
#include <cuda_fp16.h>
#include <math.h>
#include <stdint.h>

#define H 512
#define BATCH_MAX 262144

// ---------------- device scratch ----------------
__device__ float  g_u[(size_t)BATCH_MAX * 4];
__device__ __half g_h1f[(size_t)BATCH_MAX * H];   // 268 MB
__device__ __half g_h2f[(size_t)BATCH_MAX * H];   // 268 MB (pre-BN layer2)
__device__ __half g_w2f[H * H];                   // transposed [n][k]
__device__ double g_mom[14];
__device__ double g_colsum[H];
__device__ double g_colsq[H];
__device__ float  g_w1eff[4 * H];
__device__ float  g_c1[H];
__device__ float  g_scale2[H];
__device__ float  g_shift2[H];

// ---------------- PTX helpers (baseline ISA only) ----------------
__device__ __forceinline__ uint32_t smem_to_u32(const void* p) {
    uint32_t a;
    asm("{ .reg .u64 t; cvta.to.shared.u64 t, %1; cvt.u32.u64 %0, t; }" : "=r"(a) : "l"(p));
    return a;
}
__device__ __forceinline__ void ldsm4(uint32_t* r, uint32_t addr) {
    asm volatile("ldmatrix.sync.aligned.m8n8.x4.shared.b16 {%0,%1,%2,%3}, [%4];"
        : "=r"(r[0]), "=r"(r[1]), "=r"(r[2]), "=r"(r[3]) : "r"(addr));
}
__device__ __forceinline__ void mma_f16(float* d, const uint32_t* a, const uint32_t* b) {
    asm volatile("mma.sync.aligned.m16n8k16.row.col.f32.f16.f16.f32 "
        "{%0,%1,%2,%3}, {%4,%5,%6,%7}, {%8,%9}, {%0,%1,%2,%3};"
        : "+f"(d[0]), "+f"(d[1]), "+f"(d[2]), "+f"(d[3])
        : "r"(a[0]), "r"(a[1]), "r"(a[2]), "r"(a[3]), "r"(b[0]), "r"(b[1]));
}
__device__ __forceinline__ void cp16(uint32_t dst, const void* src) {
    asm volatile("cp.async.cg.shared.global [%0], [%1], 16;" :: "r"(dst), "l"(src));
}
#define CP_COMMIT() asm volatile("cp.async.commit_group;" ::: "memory")
#define CP_WAIT(n)  asm volatile("cp.async.wait_group %0;" :: "n"(n) : "memory")

// ---------------- math helpers ----------------
__device__ __forceinline__ float fast_tanh(float x) {
    float a = fabsf(x);
    float e = __expf(2.0f * a);
    float r = 1.0f - __fdividef(2.0f, e + 1.0f);
    return copysignf(r, x);
}
__device__ __forceinline__ float bilerp(const float* sts, const float* stab,
                                        float xq, int j, float ty) {
    xq = fminf(fmaxf(xq, sts[0]), sts[8]);
    int ii = 0;
#pragma unroll
    for (int k = 1; k < 9; k++) if (xq >= sts[k]) ii = k;
    if (ii > 7) ii = 7;
    float tx  = (xq - sts[ii]) / (sts[ii + 1] - sts[ii]);
    float f00 = stab[ii * 14 + j], f01 = stab[ii * 14 + j + 1];
    float f10 = stab[(ii + 1) * 14 + j], f11 = stab[(ii + 1) * 14 + j + 1];
    return f00 * (1.f - tx) * (1.f - ty) + f10 * tx * (1.f - ty)
         + f01 * (1.f - tx) * ty + f11 * tx * ty;
}

// ---------------- K0 ----------------
__global__ void k_zero() {
    int t = blockIdx.x * blockDim.x + threadIdx.x;
    if (t < 14) g_mom[t] = 0.0;
    if (t < H) { g_colsum[t] = 0.0; g_colsq[t] = 0.0; }
}

// ---------------- K1: features + 14 moments ----------------
__global__ void k_moments(const float* __restrict__ x, const float* __restrict__ ts,
                          const float* __restrict__ te, const float* __restrict__ tab, int M) {
    __shared__ float sts[9], ste[14], stab[126];
    int tid = threadIdx.x;
    if (tid < 9)   sts[tid]  = ts[tid];
    if (tid < 14)  ste[tid]  = te[tid];
    if (tid < 126) stab[tid] = tab[tid];
    __syncthreads();
    int i = blockIdx.x * blockDim.x + tid;
    float u0 = 0.f, u1 = 0.f, u2 = 0.f, u3 = 0.f;
    if (i < M) {
        const float* xr = x + (size_t)i * 15;
        float amb = xr[1], sfl = xr[2], sfr = xr[3];
        float incar = xr[8], tb = xr[9], tc = xr[10];
        float yq = fminf(fmaxf(amb, ste[0]), ste[13]);
        int j = 0;
#pragma unroll
        for (int k = 1; k < 14; k++) if (yq >= ste[k]) j = k;
        if (j > 12) j = 12;
        float ty = (yq - ste[j]) / (ste[j + 1] - ste[j]);
        u0 = bilerp(sts, stab, sfl, j, ty) - incar;
        u1 = bilerp(sts, stab, sfr, j, ty) - incar;
        u2 = amb;
        u3 = tb - tc;
        *(float4*)(g_u + (size_t)i * 4) = make_float4(u0, u1, u2, u3);
    }
    double vals[14];
    vals[0] = u0; vals[1] = u1; vals[2] = u2; vals[3] = u3;
    vals[4]  = (double)u0 * u0; vals[5]  = (double)u0 * u1;
    vals[6]  = (double)u0 * u2; vals[7]  = (double)u0 * u3;
    vals[8]  = (double)u1 * u1; vals[9]  = (double)u1 * u2;
    vals[10] = (double)u1 * u3; vals[11] = (double)u2 * u2;
    vals[12] = (double)u2 * u3; vals[13] = (double)u3 * u3;
#pragma unroll
    for (int q = 0; q < 14; q++) {
        double v = vals[q];
#pragma unroll
        for (int o = 16; o > 0; o >>= 1) v += __shfl_down_sync(0xffffffffu, v, o);
        if ((tid & 31) == 0) atomicAdd(&g_mom[q], v);
    }
}

// ---------------- K1b: analytic BN1 ----------------
__global__ void k_l1prep(const float* __restrict__ w1, const float* __restrict__ b1,
                         const float* __restrict__ g1, const float* __restrict__ beta1, int M) {
    int j = blockIdx.x * blockDim.x + threadIdx.x;
    if (j >= H) return;
    double invB = 1.0 / (double)M;
    double m[4];
#pragma unroll
    for (int k = 0; k < 4; k++) m[k] = g_mom[k] * invB;
    double C[4][4];
    int idx = 4;
#pragma unroll
    for (int k = 0; k < 4; k++)
#pragma unroll
        for (int l = k; l < 4; l++) {
            double c = g_mom[idx++] * invB - m[k] * m[l];
            C[k][l] = c; C[l][k] = c;
        }
    float w[4];
#pragma unroll
    for (int k = 0; k < 4; k++) w[k] = w1[k * H + j];
    double mu = (double)b1[j];
#pragma unroll
    for (int k = 0; k < 4; k++) mu += m[k] * (double)w[k];
    double var = 0.0;
#pragma unroll
    for (int k = 0; k < 4; k++)
#pragma unroll
        for (int l = 0; l < 4; l++) var += (double)w[k] * (double)w[l] * C[k][l];
    float A = g1[j] * rsqrtf((float)var + 1e-5f);
#pragma unroll
    for (int k = 0; k < 4; k++) g_w1eff[k * H + j] = A * w[k];
    g_c1[j] = beta1[j] + A * (b1[j] - (float)mu);
}

// ---------------- K1c: convert + transpose w2 -> [n][k] fp16 ----------------
__global__ void k_w2split(const float* __restrict__ w2) {
    int idx = blockIdx.x * 256 + threadIdx.x;
    int k = idx >> 9, n = idx & (H - 1);
    float v = __ldg(&w2[(size_t)k * H + n]);
    g_w2f[(size_t)n * H + k] = __float2half_rn(v);
}

// ---------------- K2a: h1 = tanh(u @ w1eff + c1), fp16 ----------------
__global__ __launch_bounds__(256) void k_h1(int M) {
    __shared__ float w1s[4 * H], c1s[H];
    int tid = threadIdx.x;
    for (int t = tid; t < 4 * H; t += 256) w1s[t] = g_w1eff[t];
    for (int t = tid; t < H;     t += 256) c1s[t] = g_c1[t];
    __syncthreads();
    int row0 = blockIdx.x * 32;
    int j0 = (tid & 63) * 8;
#pragma unroll
    for (int pass = 0; pass < 8; pass++) {
        int r = row0 + pass * 4 + (tid >> 6);
        if (r >= M) continue;
        float4 u = *(const float4*)(g_u + (size_t)r * 4);
        __half hv[8];
#pragma unroll
        for (int i = 0; i < 8; i++) {
            int j = j0 + i;
            float v = c1s[j] + u.x * w1s[j] + u.y * w1s[H + j]
                             + u.z * w1s[2 * H + j] + u.w * w1s[3 * H + j];
            hv[i] = __float2half_rn(fast_tanh(v));
        }
        *(uint4*)(g_h1f + (size_t)r * H + j0) = *(uint4*)hv;
    }
}

// ---------------- K2b: 1-term fp16 warp-MMA GEMM + fused column stats ----------
// CTA 128x128, 8 warps (4m x 2n), K-chunk 32, 8 chunks, 4-stage cp.async pipeline.
// grid = (4 col blocks, M/128 row blocks) for L2 reuse of A.
#define PADB 80
#define STG_A 0
#define STG_B 10240
#define STG_SZ 20480
#define SMEM_GEMM (4 * STG_SZ)

__global__ void __launch_bounds__(256, 2) k_gemm_mma(const float* __restrict__ b2, int M) {
    extern __shared__ __align__(16) char smem[];
    uint32_t sb = smem_to_u32(smem);
    int tid = threadIdx.x, lane = tid & 31, wid = tid >> 5;
    int wm = wid & 3, wn = wid >> 2;
    int colBase = blockIdx.x * 128;
    int rowBase = blockIdx.y * 128;

    uint32_t a_off = ((lane & 7) + ((lane >> 3) & 1) * 8) * PADB + ((lane >> 4) & 1) * 16;
    uint32_t b_off = ((lane & 7) + ((lane >> 4) & 1) * 8) * PADB + ((lane >> 3) & 1) * 16;

    float acc[2][8][4];
#pragma unroll
    for (int i = 0; i < 2; i++)
#pragma unroll
        for (int j = 0; j < 8; j++)
#pragma unroll
            for (int q = 0; q < 4; q++) acc[i][j][q] = 0.0f;

#define LOAD_CHUNK(c, s) do {                                                     \
        int k0_ = (c) * 32;                                                       \
        uint32_t base_ = sb + (s) * STG_SZ;                                       \
        _Pragma("unroll")                                                         \
        for (int i_ = tid; i_ < 512; i_ += 256) {                                 \
            int row_ = i_ >> 2, seg_ = i_ & 3;                                    \
            int rr_ = rowBase + row_; if (rr_ >= M) rr_ = M - 1;                  \
            cp16(base_ + STG_A + row_ * PADB + seg_ * 16,                         \
                 g_h1f + (size_t)rr_ * H + k0_ + seg_ * 8);                       \
        }                                                                         \
        _Pragma("unroll")                                                         \
        for (int i_ = tid; i_ < 512; i_ += 256) {                                 \
            int n_ = i_ >> 2, seg_ = i_ & 3;                                      \
            cp16(base_ + STG_B + n_ * PADB + seg_ * 16,                           \
                 g_w2f + (size_t)(colBase + n_) * H + k0_ + seg_ * 8);            \
        }                                                                         \
    } while (0)

    LOAD_CHUNK(0, 0); CP_COMMIT();
    LOAD_CHUNK(1, 1); CP_COMMIT();
    LOAD_CHUNK(2, 2); CP_COMMIT();

    for (int c = 0; c < 16; c++) {
        CP_WAIT(2);
        __syncthreads();
        if (c + 3 < 16) LOAD_CHUNK(c + 3, (c + 3) & 3);
        CP_COMMIT();

        uint32_t stg = sb + (c & 3) * STG_SZ;
        uint32_t aP = stg + STG_A + (wm * 32) * PADB + a_off;
        uint32_t bP = stg + STG_B + (wn * 64) * PADB + b_off;
#pragma unroll
        for (int kk = 0; kk < 2; kk++) {
            uint32_t kb = kk * 32;
            uint32_t a0[4], a1[4];
            ldsm4(a0, aP + kb);
            ldsm4(a1, aP + 16 * PADB + kb);
#pragma unroll
            for (int nq = 0; nq < 4; nq++) {
                uint32_t bq[4];
                ldsm4(bq, bP + nq * 16 * PADB + kb);
#pragma unroll
                for (int hh = 0; hh < 2; hh++) {
                    int nt = nq * 2 + hh;
                    mma_f16(acc[0][nt], a0, &bq[hh * 2]);
                    mma_f16(acc[1][nt], a1, &bq[hh * 2]);
                }
            }
        }
    }
    __syncthreads();

    // ---- epilogue: bias add, fp16 h2 store, fused column stats ----
    float* s_sum = (float*)smem;
    float* s_sq  = (float*)smem + 128;
    if (tid < 128) { s_sum[tid] = 0.f; s_sq[tid] = 0.f; }
    __syncthreads();

    int gid = lane >> 2, t4 = lane & 3;
#pragma unroll
    for (int nt = 0; nt < 8; nt++) {
        int colLocal = wn * 64 + nt * 8 + t4 * 2;
        int col = colBase + colLocal;
        float2 bb = *(const float2*)(b2 + col);
        float s0 = 0.f, s1 = 0.f, q0 = 0.f, q1 = 0.f;
#pragma unroll
        for (int mt = 0; mt < 2; mt++) {
            int r1 = rowBase + wm * 32 + mt * 16 + gid;
            int r2 = r1 + 8;
            float v00 = acc[mt][nt][0] + bb.x, v01 = acc[mt][nt][1] + bb.y;
            float v10 = acc[mt][nt][2] + bb.x, v11 = acc[mt][nt][3] + bb.y;
            if (r1 < M) *(__half2*)(g_h2f + (size_t)r1 * H + col) =
                __floats2half2_rn(v00, v01);
            if (r2 < M) *(__half2*)(g_h2f + (size_t)r2 * H + col) =
                __floats2half2_rn(v10, v11);
            s0 += v00 + v10; s1 += v01 + v11;
            q0 += v00 * v00 + v10 * v10;
            q1 += v01 * v01 + v11 * v11;
        }
#pragma unroll
        for (int o = 16; o >= 4; o >>= 1) {
            s0 += __shfl_down_sync(0xffffffffu, s0, o);
            s1 += __shfl_down_sync(0xffffffffu, s1, o);
            q0 += __shfl_down_sync(0xffffffffu, q0, o);
            q1 += __shfl_down_sync(0xffffffffu, q1, o);
        }
        if (lane < 4) {
            int cl = wn * 64 + nt * 8 + lane * 2;
            atomicAdd(&s_sum[cl],     s0);
            atomicAdd(&s_sum[cl + 1], s1);
            atomicAdd(&s_sq[cl],      q0);
            atomicAdd(&s_sq[cl + 1],  q1);
        }
    }
    __syncthreads();
    if (tid < 128) {
        atomicAdd(&g_colsum[colBase + tid], (double)s_sum[tid]);
        atomicAdd(&g_colsq[colBase + tid],  (double)s_sq[tid]);
    }
}

// ---------------- K2d: BN2 scale/shift ----------------
__global__ void k_l2prep(const float* __restrict__ g2, const float* __restrict__ beta2, int M) {
    int j = blockIdx.x * blockDim.x + threadIdx.x;
    if (j >= H) return;
    double mu  = g_colsum[j] / (double)M;
    double var = g_colsq[j] / (double)M - mu * mu;
    float s = g2[j] * rsqrtf((float)var + 1e-5f);
    g_scale2[j] = s;
    g_shift2[j] = beta2[j] - (float)mu * s;
}

// ---------------- K3: out = tanh(s*h2pre + t) @ w3 + b3 ----------------
__global__ void k_out(const float* __restrict__ w3, const float* __restrict__ b3,
                      float* __restrict__ out, int M) {
    __shared__ float sw[H], ss[H], sh[H];
    int tid = threadIdx.x;
    for (int t = tid; t < H; t += blockDim.x) {
        sw[t] = w3[t]; ss[t] = g_scale2[t]; sh[t] = g_shift2[t];
    }
    __syncthreads();
    int warp = tid >> 5, lane = tid & 31;
    int row = blockIdx.x * 8 + warp;
    if (row >= M) return;
    const __half2* hr = (const __half2*)(g_h2f + (size_t)row * H);
    float acc = 0.0f;
#pragma unroll
    for (int t = 0; t < 8; t++) {
        int p = t * 32 + lane;
        float2 hv = __half22float2(hr[p]);
        int j = p * 2;
        float v0 = fast_tanh(ss[j] * hv.x + sh[j]);
        float v1 = fast_tanh(ss[j + 1] * hv.y + sh[j + 1]);
        acc += v0 * sw[j] + v1 * sw[j + 1];
    }
#pragma unroll
    for (int o = 16; o > 0; o >>= 1) acc += __shfl_down_sync(0xffffffffu, acc, o);
    if (lane == 0) out[row] = acc + b3[0];
}

// ---------------- launch ----------------
extern "C" void kernel_launch(void* const* d_in, const int* in_sizes, int n_in,
                              void* d_out, int out_size) {
    const float* x     = (const float*)d_in[0];
    const float* ts    = (const float*)d_in[1];
    const float* te    = (const float*)d_in[2];
    const float* tab   = (const float*)d_in[3];
    const float* w1    = (const float*)d_in[4];
    const float* b1    = (const float*)d_in[5];
    const float* g1    = (const float*)d_in[6];
    const float* beta1 = (const float*)d_in[7];
    const float* w2    = (const float*)d_in[8];
    const float* b2    = (const float*)d_in[9];
    const float* g2    = (const float*)d_in[10];
    const float* beta2 = (const float*)d_in[11];
    const float* w3    = (const float*)d_in[12];
    const float* b3    = (const float*)d_in[13];
    float* out = (float*)d_out;

    int M = in_sizes[0] / 15;

    cudaFuncSetAttribute(k_gemm_mma, cudaFuncAttributeMaxDynamicSharedMemorySize, SMEM_GEMM);

    k_zero<<<2, 256>>>();
    k_moments<<<(M + 255) / 256, 256>>>(x, ts, te, tab, M);
    k_l1prep<<<2, 256>>>(w1, b1, g1, beta1, M);
    k_w2split<<<(H * H) / 256, 256>>>(w2);
    k_h1<<<(M + 31) / 32, 256>>>(M);
    k_gemm_mma<<<dim3(4, (M + 127) / 128), 256, SMEM_GEMM>>>(b2, M);
    k_l2prep<<<2, 256>>>(g2, beta2, M);
    k_out<<<(M + 7) / 8, 256>>>(w3, b3, out, M);
}